// round 13
// baseline (speedup 1.0000x reference)
#include <cuda_runtime.h>
#include <cuda_fp16.h>
#include <math.h>
#include <stdint.h>

#define T_TOKENS 16384
#define HID      640
#define NQH      10
#define NKVH     2
#define HD       64
#define SEQ      512
#define BATCH    32
#define KVDIM    128

// ---------------- scratch ----------------
__device__ __align__(16) int8_t g_xq_q[T_TOKENS * HID];
__device__ __align__(16) int8_t g_xq_k[T_TOKENS * HID];
__device__ __align__(16) int8_t g_xq_v[T_TOKENS * HID];
__device__ __align__(16) int8_t g_xq_o[T_TOKENS * HID];
__device__ __align__(16) int8_t g_wq_q[HID * HID];
__device__ __align__(16) int8_t g_wq_k[KVDIM * HID];
__device__ __align__(16) int8_t g_wq_v[KVDIM * HID];
__device__ __align__(16) int8_t g_wq_o[HID * HID];
__device__ float g_gamma_q[T_TOKENS];
__device__ float g_gamma_k[T_TOKENS];
__device__ float g_gamma_v[T_TOKENS];
__device__ float g_gamma_o[T_TOKENS];
__device__ float g_alpha[4];
__device__ __align__(16) __half g_qh[BATCH * NQH * SEQ * HD];
__device__ __align__(16) __half g_ql[BATCH * NQH * SEQ * HD];
__device__ __align__(16) __half g_kh[BATCH * NKVH * SEQ * HD];
__device__ __align__(16) __half g_kl[BATCH * NKVH * SEQ * HD];
__device__ __align__(16) __half g_vh[BATCH * NKVH * SEQ * HD];
__device__ __align__(16) __half g_vl[BATCH * NKVH * SEQ * HD];
__device__ float g_att[T_TOKENS * HID];
__device__ float g_cos[SEQ * 32];
__device__ float g_sin[SEQ * 32];

// ---------------- reduction helpers ----------------
__device__ __forceinline__ float warp_red(float v, int op) {
#pragma unroll
    for (int o = 16; o; o >>= 1) {
        float t = __shfl_xor_sync(0xffffffffu, v, o);
        v = op ? fmaxf(v, t) : v + t;
    }
    return v;
}
__device__ __forceinline__ float block_reduce(float v, int op, float* sm, int nwarps) {
    int lane = threadIdx.x & 31, w = threadIdx.x >> 5;
    v = warp_red(v, op);
    if (!lane) sm[w] = v;
    __syncthreads();
    if (w == 0) {
        v = (lane < nwarps) ? sm[lane] : (op ? -INFINITY : 0.0f);
        v = warp_red(v, op);
        if (!lane) sm[0] = v;
    }
    __syncthreads();
    v = sm[0];
    __syncthreads();
    return v;
}

// ---------------- fused prep: alpha (0-3) + rope tables (4-67) + act quant ----
// 256 threads everywhere. act-quant blocks handle 8 tokens (warp per token).
#define PREP_BLOCKS (4 + 64 + T_TOKENS / 8)
__global__ __launch_bounds__(256) void prep_fused(
    const float* __restrict__ x, const float* __restrict__ nw,
    const float* __restrict__ qg, const float* __restrict__ kg, const float* __restrict__ vg,
    const float* __restrict__ qw, const float* __restrict__ kw,
    const float* __restrict__ vw, const float* __restrict__ ow) {
    int bid = blockIdx.x;
    if (bid < 4) {
        __shared__ float sm[8];
        int which = bid;
        const float* w = which == 0 ? qw : which == 1 ? kw : which == 2 ? vw : ow;
        int n = (which == 1 || which == 2) ? (KVDIM * HID) : (HID * HID);
        float s = 0.0f;
        for (int i = threadIdx.x; i < n; i += 256) s += fabsf(w[i]);
        s = block_reduce(s, 0, sm, 8);
        if (threadIdx.x == 0) g_alpha[which] = fmaxf(s / (float)n, 1e-10f);
        return;
    }
    if (bid < 68) {
        int idx = (bid - 4) * 256 + threadIdx.x;   // 64*256 = 16384 = SEQ*32
        int l = idx >> 5, p = idx & 31;
        double freq = exp2(-(double)p * (18.93156856932417 / 32.0));  // 500000^(-p/32)
        double a = (double)l * freq;
        const double TWO_PI = 6.283185307179586476925287;
        double r = a - floor(a * (1.0 / TWO_PI)) * TWO_PI;
        float rf = (float)r;
        g_cos[idx] = cosf(rf);
        g_sin[idx] = sinf(rf);
        return;
    }
    // activation double-rmsnorm + int8 quant, warp per token
    int warp = threadIdx.x >> 5, lane = threadIdx.x & 31;
    int t = (bid - 68) * 8 + warp;
    const float4* xr = (const float4*)(x + (size_t)t * HID);
    const float4* nw4 = (const float4*)nw;
    float4 v[5], h[5];
    float ss = 0.0f;
#pragma unroll
    for (int j = 0; j < 5; j++) {
        v[j] = xr[lane + j * 32];
        ss += v[j].x * v[j].x + v[j].y * v[j].y + v[j].z * v[j].z + v[j].w * v[j].w;
    }
    ss = warp_red(ss, 0);
    float rinv = rsqrtf(ss / (float)HID + 1e-6f);
    float s2 = 0.0f;
#pragma unroll
    for (int j = 0; j < 5; j++) {
        float4 g4 = nw4[lane + j * 32];
        h[j].x = v[j].x * rinv * g4.x; h[j].y = v[j].y * rinv * g4.y;
        h[j].z = v[j].z * rinv * g4.z; h[j].w = v[j].w * rinv * g4.w;
        s2 += h[j].x * h[j].x + h[j].y * h[j].y + h[j].z * h[j].z + h[j].w * h[j].w;
    }
    s2 = warp_red(s2, 0);
    float rinv2 = rsqrtf(s2 / (float)HID + 1e-6f);

    const float* gains[3] = { qg, kg, vg };
    int8_t* dsts[3] = { g_xq_q, g_xq_k, g_xq_v };
    float* gmas[3] = { g_gamma_q, g_gamma_k, g_gamma_v };
#pragma unroll
    for (int which = 0; which < 3; which++) {
        const float4* g4p = (const float4*)gains[which];
        float4 hq[5];
        float gm = 0.0f;
#pragma unroll
        for (int j = 0; j < 5; j++) {
            float4 g4 = g4p[lane + j * 32];
            hq[j].x = h[j].x * rinv2 * g4.x; hq[j].y = h[j].y * rinv2 * g4.y;
            hq[j].z = h[j].z * rinv2 * g4.z; hq[j].w = h[j].w * rinv2 * g4.w;
            gm = fmaxf(gm, fmaxf(fmaxf(fabsf(hq[j].x), fabsf(hq[j].y)),
                                 fmaxf(fabsf(hq[j].z), fabsf(hq[j].w))));
        }
        gm = warp_red(gm, 1);
        gm = fmaxf(gm, 1e-10f);
        float sc = 127.0f / gm;
        char4* dst4 = (char4*)(dsts[which] + (size_t)t * HID);
#pragma unroll
        for (int j = 0; j < 5; j++) {
            char4 q;
            q.x = (int8_t)fminf(fmaxf(rintf(hq[j].x * sc), -128.0f), 127.0f);
            q.y = (int8_t)fminf(fmaxf(rintf(hq[j].y * sc), -128.0f), 127.0f);
            q.z = (int8_t)fminf(fmaxf(rintf(hq[j].z * sc), -128.0f), 127.0f);
            q.w = (int8_t)fminf(fmaxf(rintf(hq[j].w * sc), -128.0f), 127.0f);
            dst4[lane + j * 32] = q;
        }
        if (lane == 0) gmas[which][t] = gm;
    }
}

// ---------------- weight ternary quant ----------------
__global__ void wquant_all(const float* __restrict__ qw, const float* __restrict__ kw,
                           const float* __restrict__ vw, const float* __restrict__ ow) {
    int idx = blockIdx.x * blockDim.x + threadIdx.x;
    const float* w; int8_t* dst; int off; int which;
    const int nQ = HID * HID, nK = KVDIM * HID;
    if (idx < nQ)                       { which = 0; w = qw; dst = g_wq_q; off = idx; }
    else if (idx < nQ + nK)             { which = 1; w = kw; dst = g_wq_k; off = idx - nQ; }
    else if (idx < nQ + 2 * nK)         { which = 2; w = vw; dst = g_wq_v; off = idx - nQ - nK; }
    else if (idx < 2 * nQ + 2 * nK)     { which = 3; w = ow; dst = g_wq_o; off = idx - nQ - 2 * nK; }
    else return;
    float a = g_alpha[which];
    float q = rintf(w[off] / a);
    q = fminf(fmaxf(q, -1.0f), 1.0f);
    dst[off] = (int8_t)q;
}

// ---------------- activation quant (O path) ----------------
__global__ __launch_bounds__(256) void act_quant_o(const float* __restrict__ og) {
    int warp = threadIdx.x >> 5, lane = threadIdx.x & 31;
    int t = blockIdx.x * 8 + warp;
    const float4* xr = (const float4*)(g_att + (size_t)t * HID);
    const float4* og4 = (const float4*)og;
    float4 v[5], hq[5];
    float ss = 0.0f;
#pragma unroll
    for (int j = 0; j < 5; j++) {
        v[j] = xr[lane + j * 32];
        ss += v[j].x * v[j].x + v[j].y * v[j].y + v[j].z * v[j].z + v[j].w * v[j].w;
    }
    ss = warp_red(ss, 0);
    float rinv = rsqrtf(ss / (float)HID + 1e-6f);
    float gm = 0.0f;
#pragma unroll
    for (int j = 0; j < 5; j++) {
        float4 g4 = og4[lane + j * 32];
        hq[j].x = v[j].x * rinv * g4.x; hq[j].y = v[j].y * rinv * g4.y;
        hq[j].z = v[j].z * rinv * g4.z; hq[j].w = v[j].w * rinv * g4.w;
        gm = fmaxf(gm, fmaxf(fmaxf(fabsf(hq[j].x), fabsf(hq[j].y)),
                             fmaxf(fabsf(hq[j].z), fabsf(hq[j].w))));
    }
    gm = warp_red(gm, 1);
    gm = fmaxf(gm, 1e-10f);
    float sc = 127.0f / gm;
    char4* dst4 = (char4*)(g_xq_o + (size_t)t * HID);
#pragma unroll
    for (int j = 0; j < 5; j++) {
        char4 q;
        q.x = (int8_t)fminf(fmaxf(rintf(hq[j].x * sc), -128.0f), 127.0f);
        q.y = (int8_t)fminf(fmaxf(rintf(hq[j].y * sc), -128.0f), 127.0f);
        q.z = (int8_t)fminf(fmaxf(rintf(hq[j].z * sc), -128.0f), 127.0f);
        q.w = (int8_t)fminf(fmaxf(rintf(hq[j].w * sc), -128.0f), 127.0f);
        dst4[lane + j * 32] = q;
    }
    if (lane == 0) g_gamma_o[t] = gm;
}

// ---------------- mma / async helpers ----------------
__device__ __forceinline__ uint32_t smem_u32(const void* p) {
    return (uint32_t)__cvta_generic_to_shared(p);
}
__device__ __forceinline__ void ldmx4(uint32_t* r, uint32_t addr) {
    asm volatile("ldmatrix.sync.aligned.m8n8.x4.shared.b16 {%0,%1,%2,%3}, [%4];\n"
                 : "=r"(r[0]), "=r"(r[1]), "=r"(r[2]), "=r"(r[3]) : "r"(addr));
}
__device__ __forceinline__ void ldmx4t(uint32_t* r, uint32_t addr) {
    asm volatile("ldmatrix.sync.aligned.m8n8.x4.trans.shared.b16 {%0,%1,%2,%3}, [%4];\n"
                 : "=r"(r[0]), "=r"(r[1]), "=r"(r[2]), "=r"(r[3]) : "r"(addr));
}
__device__ __forceinline__ void mma_f16(float* c, const uint32_t* a, uint32_t b0, uint32_t b1) {
    asm volatile("mma.sync.aligned.m16n8k16.row.col.f32.f16.f16.f32 "
                 "{%0,%1,%2,%3}, {%4,%5,%6,%7}, {%8,%9}, {%0,%1,%2,%3};\n"
                 : "+f"(c[0]), "+f"(c[1]), "+f"(c[2]), "+f"(c[3])
                 : "r"(a[0]), "r"(a[1]), "r"(a[2]), "r"(a[3]), "r"(b0), "r"(b1));
}
__device__ __forceinline__ void mma_s8(int* c, const uint32_t* a, uint32_t b0, uint32_t b1) {
    asm volatile("mma.sync.aligned.m16n8k32.row.col.s32.s8.s8.s32 "
                 "{%0,%1,%2,%3}, {%4,%5,%6,%7}, {%8,%9}, {%0,%1,%2,%3};\n"
                 : "+r"(c[0]), "+r"(c[1]), "+r"(c[2]), "+r"(c[3])
                 : "r"(a[0]), "r"(a[1]), "r"(a[2]), "r"(a[3]), "r"(b0), "r"(b1));
}
__device__ __forceinline__ void cp16(void* s, const void* g) {
    asm volatile("cp.async.cg.shared.global [%0], [%1], 16;\n"
                 :: "r"(smem_u32(s)), "l"(g));
}
__device__ __forceinline__ void cp_commit() {
    asm volatile("cp.async.commit_group;\n");
}
template <int N>
__device__ __forceinline__ void cp_wait() {
    asm volatile("cp.async.wait_group %0;\n" :: "n"(N));
}
__device__ __forceinline__ uint32_t pack_h2(__half x, __half y) {
    __half2 h = __halves2half2(x, y);
    return *(uint32_t*)&h;
}
__device__ __forceinline__ void split_h(float x, __half& hi, __half& lo) {
    hi = __float2half_rn(x);
    lo = __float2half_rn(x - __half2float(hi));
}

// ---------------- int8 TC GEMM, cp.async double-buffered ----------------------
#define GP 144
#define GSTAGE (128 * GP)
#define GEMM_SMEM (4 * GSTAGE)   // 73728 B

__device__ __forceinline__ void imma_tile(
    const int8_t* __restrict__ A, const int8_t* __restrict__ Bw,
    int t0, int n0, uint8_t* dsm, int acc[2][8][4]) {
    int8_t* As = (int8_t*)dsm;
    int8_t* Bs = (int8_t*)dsm + 2 * GSTAGE;
    int tid = threadIdx.x, warp = tid >> 5, lane = tid & 31;
    int wm = warp >> 1, wn = warp & 1;
#pragma unroll
    for (int mt = 0; mt < 2; mt++)
#pragma unroll
        for (int nt = 0; nt < 8; nt++)
#pragma unroll
            for (int i = 0; i < 4; i++) acc[mt][nt][i] = 0;

    int row = tid >> 1;
    int sh = (tid & 1) * 4;
#pragma unroll
    for (int c = 0; c <= 5; c++) {
        if (c < 5) {
            int st = (c & 1) * GSTAGE;
#pragma unroll
            for (int s = 0; s < 4; s++) {
                int seg = sh + s;
                cp16(&As[st + row * GP + seg * 16],
                     &A[(size_t)(t0 + row) * HID + c * 128 + seg * 16]);
                cp16(&Bs[st + row * GP + seg * 16],
                     &Bw[(size_t)(n0 + row) * HID + c * 128 + seg * 16]);
            }
            cp_commit();
        }
        if (c == 0) continue;
        int cc = c - 1;
        if (c < 5) cp_wait<1>(); else cp_wait<0>();
        __syncthreads();
        int st = (cc & 1) * GSTAGE;
#pragma unroll
        for (int ks = 0; ks < 4; ks++) {
            uint32_t af[2][4];
#pragma unroll
            for (int mt = 0; mt < 2; mt++)
                ldmx4(af[mt], smem_u32(&As[st + (wm * 32 + mt * 16 + (lane & 15)) * GP +
                                            ks * 32 + (lane >> 4) * 16]));
#pragma unroll
            for (int np = 0; np < 4; np++) {
                uint32_t bf[4];
                ldmx4(bf, smem_u32(&Bs[st + (wn * 64 + np * 16 + (lane & 15)) * GP +
                                        ks * 32 + (lane >> 4) * 16]));
#pragma unroll
                for (int mt = 0; mt < 2; mt++) {
                    mma_s8(acc[mt][np * 2],     af[mt], bf[0], bf[2]);
                    mma_s8(acc[mt][np * 2 + 1], af[mt], bf[1], bf[3]);
                }
            }
        }
        __syncthreads();
    }
}

// epilogue helper: rope + fp16 hi/lo split write
__device__ __forceinline__ void write_qkv_pair(
    float v0, float v1, int r, int n, int nheads, int rope,
    __half* __restrict__ hob, __half* __restrict__ lob) {
    int head = n >> 6, d = n & 63;
    int bI = r >> 9, l = r & 511;
    if (rope) {
        int p = d >> 1;
        float c0 = g_cos[l * 32 + p], sn0 = g_sin[l * 32 + p];
        float t0f = v0 * c0 - v1 * sn0, t1f = v1 * c0 + v0 * sn0;
        v0 = t0f; v1 = t1f;
    }
    size_t i0 = (((size_t)bI * nheads + head) * SEQ + l) * HD + d;
    __half h0, h1, e0, e1;
    split_h(v0, h0, e0); split_h(v1, h1, e1);
    *(__half2*)&hob[i0] = __halves2half2(h0, h1);
    *(__half2*)&lob[i0] = __halves2half2(e0, e1);
}

// ---------------- fused QKV GEMM (pure IMMA) ----------------------------------
// blocks [0,640): Q; [640,768): K; [768,896): V
__global__ __launch_bounds__(256) void gemm_qkv() {
    extern __shared__ uint8_t dsm[];
    int bid = blockIdx.x;
    int path, bx, by;
    if (bid < 640)      { path = 0; bx = bid & 127; by = bid >> 7; }
    else if (bid < 768) { path = 1; bx = bid - 640; by = 0; }
    else                { path = 2; bx = bid - 768; by = 0; }
    const int8_t* A  = path == 0 ? g_xq_q : path == 1 ? g_xq_k : g_xq_v;
    const int8_t* Bw = path == 0 ? g_wq_q : path == 1 ? g_wq_k : g_wq_v;
    const float* gamma = path == 0 ? g_gamma_q : path == 1 ? g_gamma_k : g_gamma_v;
    __half* hob = path == 0 ? g_qh : path == 1 ? g_kh : g_vh;
    __half* lob = path == 0 ? g_ql : path == 1 ? g_kl : g_vl;
    int nheads = path == 0 ? NQH : NKVH;
    int rope   = path == 2 ? 0 : 1;
    float oscale = path == 0 ? 0.125f : 1.0f;
    int t0 = bx * 128, n0 = by * 128;
    int tid = threadIdx.x;
    float alphab = g_alpha[path] * (1.0f / 127.0f) * oscale;

    int acc[2][8][4];
    imma_tile(A, Bw, t0, n0, dsm, acc);
    int warp = tid >> 5, lane = tid & 31;
    int wm = warp >> 1, wn = warp & 1;
#pragma unroll
    for (int mt = 0; mt < 2; mt++) {
        int r0 = t0 + wm * 32 + mt * 16 + (lane >> 2);
        int r1 = r0 + 8;
        float s0 = alphab * gamma[r0];
        float s1 = alphab * gamma[r1];
#pragma unroll
        for (int nt = 0; nt < 8; nt++) {
            int n = n0 + wn * 64 + nt * 8 + (lane & 3) * 2;
            write_qkv_pair((float)acc[mt][nt][0] * s0, (float)acc[mt][nt][1] * s0,
                           r0, n, nheads, rope, hob, lob);
            write_qkv_pair((float)acc[mt][nt][2] * s1, (float)acc[mt][nt][3] * s1,
                           r1, n, nheads, rope, hob, lob);
        }
    }
}

// ---------------- O-proj GEMM (pure IMMA, float out + residual) ---------------
__global__ __launch_bounds__(256) void gemm_o(
    float* __restrict__ outf, const float* __restrict__ resid) {
    extern __shared__ uint8_t dsm[];
    int t0 = blockIdx.x * 128, n0 = blockIdx.y * 128;
    int tid = threadIdx.x;
    float alphab = g_alpha[3] * (1.0f / 127.0f);

    int acc[2][8][4];
    imma_tile(g_xq_o, g_wq_o, t0, n0, dsm, acc);
    int warp = tid >> 5, lane = tid & 31;
    int wm = warp >> 1, wn = warp & 1;
#pragma unroll
    for (int mt = 0; mt < 2; mt++) {
        int r0 = t0 + wm * 32 + mt * 16 + (lane >> 2);
        int r1 = r0 + 8;
        float s0 = alphab * g_gamma_o[r0];
        float s1 = alphab * g_gamma_o[r1];
#pragma unroll
        for (int nt = 0; nt < 8; nt++) {
            int n = n0 + wn * 64 + nt * 8 + (lane & 3) * 2;
            const float* rr0 = resid + (size_t)r0 * HID + n;
            const float* rr1 = resid + (size_t)r1 * HID + n;
            *(float2*)&outf[(size_t)r0 * HID + n] =
                make_float2((float)acc[mt][nt][0] * s0 + rr0[0],
                            (float)acc[mt][nt][1] * s0 + rr0[1]);
            *(float2*)&outf[(size_t)r1 * HID + n] =
                make_float2((float)acc[mt][nt][2] * s1 + rr1[0],
                            (float)acc[mt][nt][3] * s1 + rr1[1]);
        }
    }
}

// ---------------- attention: flash, split-fp16 mma, cp.async 2-stage ----------
#define SPITCH 72
#define ATTN_SMEM (36864 * 2)   // 73728 B
__global__ __launch_bounds__(256) void attn_mma(float* __restrict__ out) {
    extern __shared__ __half ASM[];

    int tid = threadIdx.x;
    int warp = tid >> 5, lane = tid & 31;
    int qt = blockIdx.x;
    int bh = blockIdx.y;
    int b = bh / NQH, h = bh % NQH;
    int kvh = h / (NQH / NKVH);

    size_t qoff = ((size_t)(b * NQH + h) * SEQ + qt * 128) * HD;
    size_t kvoff = (size_t)(b * NKVH + kvh) * SEQ * HD;
    const __half* gbuf[4] = { g_kh + kvoff, g_kl + kvoff, g_vh + kvoff, g_vl + kvoff };

    __half* Qh = ASM;
    __half* Ql = ASM + 9216;
#pragma unroll
    for (int i = 0; i < 4; i++) {
        int slot = tid + i * 256;
        int r = slot >> 3, seg = slot & 7;
        *(float4*)&Qh[r * SPITCH + seg * 8] = *(const float4*)&g_qh[qoff + r * 64 + seg * 8];
        *(float4*)&Ql[r * SPITCH + seg * 8] = *(const float4*)&g_ql[qoff + r * 64 + seg * 8];
    }
    __syncthreads();

    {
        __half* sb = ASM + 18432;
#pragma unroll
        for (int i = 0; i < 8; i++) {
            int slot = tid + i * 256;
            int bufi = slot >> 9, r = (slot >> 3) & 63, seg = slot & 7;
            cp16(&sb[bufi * 4608 + r * SPITCH + seg * 8], &gbuf[bufi][r * 64 + seg * 8]);
        }
        cp_commit();
    }

    uint32_t qah[4][4], qal[4][4];
    int m0 = warp * 16;
#pragma unroll
    for (int kc = 0; kc < 4; kc++) {
        int r = m0 + (lane & 15), c = kc * 16 + (lane >> 4) * 8;
        ldmx4(qah[kc], smem_u32(&Qh[r * SPITCH + c]));
        ldmx4(qal[kc], smem_u32(&Ql[r * SPITCH + c]));
    }
    __syncthreads();

    float oacc[8][4];
#pragma unroll
    for (int nt = 0; nt < 8; nt++)
#pragma unroll
        for (int i = 0; i < 4; i++) oacc[nt][i] = 0.0f;
    float mrow0 = -1e30f, mrow1 = -1e30f, lrow0 = 0.0f, lrow1 = 0.0f;

    for (int kt = 0; kt < 8; kt++) {
        if (kt < 7) {
            __half* sb = ASM + (kt & 1) * 18432;
#pragma unroll
            for (int i = 0; i < 8; i++) {
                int slot = tid + i * 256;
                int bufi = slot >> 9, r = (slot >> 3) & 63, seg = slot & 7;
                cp16(&sb[bufi * 4608 + r * SPITCH + seg * 8],
                     &gbuf[bufi][((kt + 1) * 64 + r) * 64 + seg * 8]);
            }
            cp_commit();
            cp_wait<1>();
        } else {
            cp_wait<0>();
        }
        __syncthreads();
        __half* sb = ASM + ((kt + 1) & 1) * 18432;
        __half* Khs = sb;
        __half* Kls = sb + 4608;
        __half* Vhs = sb + 9216;
        __half* Vls = sb + 13824;

        float sacc[8][4];
#pragma unroll
        for (int nt = 0; nt < 8; nt++)
#pragma unroll
            for (int i = 0; i < 4; i++) sacc[nt][i] = 0.0f;
        int g = lane >> 3;
        int n_off = (g >= 2) ? 8 : 0, k_off = (g & 1) * 8;
#pragma unroll
        for (int nt2 = 0; nt2 < 4; nt2++) {
#pragma unroll
            for (int kc = 0; kc < 4; kc++) {
                uint32_t kbh[4], kbl[4];
                int r = nt2 * 16 + n_off + (lane & 7), c = kc * 16 + k_off;
                ldmx4(kbh, smem_u32(&Khs[r * SPITCH + c]));
                ldmx4(kbl, smem_u32(&Kls[r * SPITCH + c]));
                mma_f16(sacc[nt2 * 2],     qah[kc], kbh[0], kbh[1]);
                mma_f16(sacc[nt2 * 2],     qah[kc], kbl[0], kbl[1]);
                mma_f16(sacc[nt2 * 2],     qal[kc], kbh[0], kbh[1]);
                mma_f16(sacc[nt2 * 2 + 1], qah[kc], kbh[2], kbh[3]);
                mma_f16(sacc[nt2 * 2 + 1], qah[kc], kbl[2], kbl[3]);
                mma_f16(sacc[nt2 * 2 + 1], qal[kc], kbh[2], kbh[3]);
            }
        }

        float mx0 = -1e30f, mx1 = -1e30f;
#pragma unroll
        for (int nt = 0; nt < 8; nt++) {
            mx0 = fmaxf(mx0, fmaxf(sacc[nt][0], sacc[nt][1]));
            mx1 = fmaxf(mx1, fmaxf(sacc[nt][2], sacc[nt][3]));
        }
        mx0 = fmaxf(mx0, __shfl_xor_sync(0xffffffffu, mx0, 1));
        mx0 = fmaxf(mx0, __shfl_xor_sync(0xffffffffu, mx0, 2));
        mx1 = fmaxf(mx1, __shfl_xor_sync(0xffffffffu, mx1, 1));
        mx1 = fmaxf(mx1, __shfl_xor_sync(0xffffffffu, mx1, 2));
        float mn0 = fmaxf(mrow0, mx0), mn1 = fmaxf(mrow1, mx1);
        float e0 = __expf(mrow0 - mn0), e1 = __expf(mrow1 - mn1);
        mrow0 = mn0; mrow1 = mn1;

        float sum0 = 0.0f, sum1 = 0.0f;
        uint32_t pah[4][4], pal[4][4];
#pragma unroll
        for (int kc2 = 0; kc2 < 4; kc2++) {
            int nta = kc2 * 2, ntb = nta + 1;
            float p[8];
            p[0] = __expf(sacc[nta][0] - mn0); p[1] = __expf(sacc[nta][1] - mn0);
            p[2] = __expf(sacc[nta][2] - mn1); p[3] = __expf(sacc[nta][3] - mn1);
            p[4] = __expf(sacc[ntb][0] - mn0); p[5] = __expf(sacc[ntb][1] - mn0);
            p[6] = __expf(sacc[ntb][2] - mn1); p[7] = __expf(sacc[ntb][3] - mn1);
            __half ph[8], pl[8];
#pragma unroll
            for (int i = 0; i < 8; i++) split_h(p[i], ph[i], pl[i]);
            sum0 += p[0] + p[1] + p[4] + p[5];
            sum1 += p[2] + p[3] + p[6] + p[7];
            pah[kc2][0] = pack_h2(ph[0], ph[1]); pal[kc2][0] = pack_h2(pl[0], pl[1]);
            pah[kc2][1] = pack_h2(ph[2], ph[3]); pal[kc2][1] = pack_h2(pl[2], pl[3]);
            pah[kc2][2] = pack_h2(ph[4], ph[5]); pal[kc2][2] = pack_h2(pl[4], pl[5]);
            pah[kc2][3] = pack_h2(ph[6], ph[7]); pal[kc2][3] = pack_h2(pl[6], pl[7]);
        }
        sum0 += __shfl_xor_sync(0xffffffffu, sum0, 1);
        sum0 += __shfl_xor_sync(0xffffffffu, sum0, 2);
        sum1 += __shfl_xor_sync(0xffffffffu, sum1, 1);
        sum1 += __shfl_xor_sync(0xffffffffu, sum1, 2);
        lrow0 = lrow0 * e0 + sum0;
        lrow1 = lrow1 * e1 + sum1;

#pragma unroll
        for (int nt = 0; nt < 8; nt++) {
            oacc[nt][0] *= e0; oacc[nt][1] *= e0;
            oacc[nt][2] *= e1; oacc[nt][3] *= e1;
        }

#pragma unroll
        for (int kc2 = 0; kc2 < 4; kc2++) {
#pragma unroll
            for (int nt2 = 0; nt2 < 4; nt2++) {
                uint32_t vbh[4], vbl[4];
                int r = kc2 * 16 + (g & 1) * 8 + (lane & 7);
                int c = nt2 * 16 + ((g >= 2) ? 8 : 0);
                ldmx4t(vbh, smem_u32(&Vhs[r * SPITCH + c]));
                ldmx4t(vbl, smem_u32(&Vls[r * SPITCH + c]));
                mma_f16(oacc[nt2 * 2],     pah[kc2], vbh[0], vbh[1]);
                mma_f16(oacc[nt2 * 2],     pah[kc2], vbl[0], vbl[1]);
                mma_f16(oacc[nt2 * 2],     pal[kc2], vbh[0], vbh[1]);
                mma_f16(oacc[nt2 * 2 + 1], pah[kc2], vbh[2], vbh[3]);
                mma_f16(oacc[nt2 * 2 + 1], pah[kc2], vbl[2], vbl[3]);
                mma_f16(oacc[nt2 * 2 + 1], pal[kc2], vbh[2], vbh[3]);
            }
        }
        __syncthreads();
    }

    float inv0 = 1.0f / lrow0, inv1 = 1.0f / lrow1;
    int r0 = qt * 128 + m0 + (lane >> 2);
    int r1 = r0 + 8;
#pragma unroll
    for (int nt = 0; nt < 8; nt++) {
        int col = h * HD + nt * 8 + (lane & 3) * 2;
        float2 v0 = make_float2(oacc[nt][0] * inv0, oacc[nt][1] * inv0);
        float2 v1 = make_float2(oacc[nt][2] * inv1, oacc[nt][3] * inv1);
        *(float2*)&out[((size_t)b * SEQ + r0) * HID + col] = v0;
        *(float2*)&out[((size_t)b * SEQ + r1) * HID + col] = v1;
    }
}

// ---------------- launch ----------------
extern "C" void kernel_launch(void* const* d_in, const int* in_sizes, int n_in,
                              void* d_out, int out_size) {
    const float* x      = (const float*)d_in[0];
    const float* norm_w = (const float*)d_in[1];
    const float* q_w    = (const float*)d_in[2];
    const float* q_g    = (const float*)d_in[3];
    const float* k_w    = (const float*)d_in[4];
    const float* k_g    = (const float*)d_in[5];
    const float* v_w    = (const float*)d_in[6];
    const float* v_g    = (const float*)d_in[7];
    const float* o_w    = (const float*)d_in[8];
    const float* o_g    = (const float*)d_in[9];
    float* out = (float*)d_out;

    void* p_att;
    cudaGetSymbolAddress(&p_att, g_att);

    cudaFuncSetAttribute(gemm_qkv, cudaFuncAttributeMaxDynamicSharedMemorySize, GEMM_SMEM);
    cudaFuncSetAttribute(gemm_o, cudaFuncAttributeMaxDynamicSharedMemorySize, GEMM_SMEM);
    cudaFuncSetAttribute(attn_mma, cudaFuncAttributeMaxDynamicSharedMemorySize, ATTN_SMEM);

    // 1. fused: weight alphas + rope tables + activation quant
    prep_fused<<<PREP_BLOCKS, 256>>>(x, norm_w, q_g, k_g, v_g, q_w, k_w, v_w, o_w);

    // 2. weight ternary quant (needs alpha)
    wquant_all<<<(2 * HID * HID + 2 * KVDIM * HID + 255) / 256, 256>>>(q_w, k_w, v_w, o_w);

    // 3. fused QKV GEMMs (pure IMMA; rope + hi/lo split epilogue)
    gemm_qkv<<<896, 256, GEMM_SMEM>>>();

    // 4. attention  [profiled slot]
    attn_mma<<<dim3(SEQ / 128, BATCH * NQH), 256, ATTN_SMEM>>>((float*)p_att);

    // 5. O-proj quant + GEMM + residual
    act_quant_o<<<T_TOKENS / 8, 256>>>(o_g);
    gemm_o<<<dim3(128, 5), 256, GEMM_SMEM>>>(out, x);
}

// round 15
// speedup vs baseline: 1.0956x; 1.0956x over previous
#include <cuda_runtime.h>
#include <cuda_fp16.h>
#include <math.h>
#include <stdint.h>

#define T_TOKENS 16384
#define HID      640
#define NQH      10
#define NKVH     2
#define HD       64
#define SEQ      512
#define BATCH    32
#define KVDIM    128

// ---------------- scratch ----------------
__device__ __align__(16) int8_t g_xq_q[T_TOKENS * HID];
__device__ __align__(16) int8_t g_xq_k[T_TOKENS * HID];
__device__ __align__(16) int8_t g_xq_v[T_TOKENS * HID];
__device__ __align__(16) int8_t g_xq_o[T_TOKENS * HID];
__device__ __align__(16) int8_t g_wq_q[HID * HID];
__device__ __align__(16) int8_t g_wq_k[KVDIM * HID];
__device__ __align__(16) int8_t g_wq_v[KVDIM * HID];
__device__ __align__(16) int8_t g_wq_o[HID * HID];
__device__ float g_gamma_q[T_TOKENS];
__device__ float g_gamma_k[T_TOKENS];
__device__ float g_gamma_v[T_TOKENS];
__device__ float g_gamma_o[T_TOKENS];
__device__ float g_alpha[4];
__device__ __align__(16) __half g_qh[BATCH * NQH * SEQ * HD];
__device__ __align__(16) __half g_ql[BATCH * NQH * SEQ * HD];
__device__ __align__(16) __half g_kh[BATCH * NKVH * SEQ * HD];
__device__ __align__(16) __half g_kl[BATCH * NKVH * SEQ * HD];
__device__ __align__(16) __half g_vh[BATCH * NKVH * SEQ * HD];
__device__ __align__(16) __half g_vl[BATCH * NKVH * SEQ * HD];
__device__ float g_att[T_TOKENS * HID];
__device__ float g_cos[SEQ * 32];
__device__ float g_sin[SEQ * 32];

// ---------------- reduction helpers ----------------
__device__ __forceinline__ float warp_red(float v, int op) {
#pragma unroll
    for (int o = 16; o; o >>= 1) {
        float t = __shfl_xor_sync(0xffffffffu, v, o);
        v = op ? fmaxf(v, t) : v + t;
    }
    return v;
}
__device__ __forceinline__ float block_reduce(float v, int op, float* sm, int nwarps) {
    int lane = threadIdx.x & 31, w = threadIdx.x >> 5;
    v = warp_red(v, op);
    if (!lane) sm[w] = v;
    __syncthreads();
    if (w == 0) {
        v = (lane < nwarps) ? sm[lane] : (op ? -INFINITY : 0.0f);
        v = warp_red(v, op);
        if (!lane) sm[0] = v;
    }
    __syncthreads();
    v = sm[0];
    __syncthreads();
    return v;
}

// ---------------- prep: weight alpha (blocks 0-3) + rope tables ----------------
__global__ __launch_bounds__(1024) void prep_all(
    const float* __restrict__ qw, const float* __restrict__ kw,
    const float* __restrict__ vw, const float* __restrict__ ow) {
    if (blockIdx.x < 4) {
        __shared__ float sm[32];
        int which = blockIdx.x;
        const float* w = which == 0 ? qw : which == 1 ? kw : which == 2 ? vw : ow;
        int n = (which == 1 || which == 2) ? (KVDIM * HID) : (HID * HID);
        float s = 0.0f;
        for (int i = threadIdx.x; i < n; i += 1024) s += fabsf(w[i]);
        s = block_reduce(s, 0, sm, 32);
        if (threadIdx.x == 0) g_alpha[which] = fmaxf(s / (float)n, 1e-10f);
    } else {
        int idx = (blockIdx.x - 4) * 1024 + threadIdx.x;
        if (idx >= SEQ * 32) return;
        int l = idx >> 5, p = idx & 31;
        double freq = exp2(-(double)p * (18.93156856932417 / 32.0));  // 500000^(-p/32)
        double a = (double)l * freq;
        const double TWO_PI = 6.283185307179586476925287;
        double r = a - floor(a * (1.0 / TWO_PI)) * TWO_PI;
        float rf = (float)r;
        g_cos[idx] = cosf(rf);
        g_sin[idx] = sinf(rf);
    }
}

// ---------------- weight ternary quant ----------------
__global__ void wquant_all(const float* __restrict__ qw, const float* __restrict__ kw,
                           const float* __restrict__ vw, const float* __restrict__ ow) {
    int idx = blockIdx.x * blockDim.x + threadIdx.x;
    const float* w; int8_t* dst; int off; int which;
    const int nQ = HID * HID, nK = KVDIM * HID;
    if (idx < nQ)                       { which = 0; w = qw; dst = g_wq_q; off = idx; }
    else if (idx < nQ + nK)             { which = 1; w = kw; dst = g_wq_k; off = idx - nQ; }
    else if (idx < nQ + 2 * nK)         { which = 2; w = vw; dst = g_wq_v; off = idx - nQ - nK; }
    else if (idx < 2 * nQ + 2 * nK)     { which = 3; w = ow; dst = g_wq_o; off = idx - nQ - 2 * nK; }
    else return;
    float a = g_alpha[which];
    float q = rintf(w[off] / a);
    q = fminf(fmaxf(q, -1.0f), 1.0f);
    dst[off] = (int8_t)q;
}

// ---------------- activation quant, warp-per-token (QKV) ----------------
__global__ __launch_bounds__(256) void act_quant_qkv(
    const float* __restrict__ x, const float* __restrict__ nw,
    const float* __restrict__ qg, const float* __restrict__ kg, const float* __restrict__ vg) {
    int warp = threadIdx.x >> 5, lane = threadIdx.x & 31;
    int t = blockIdx.x * 8 + warp;
    const float4* xr = (const float4*)(x + (size_t)t * HID);
    const float4* nw4 = (const float4*)nw;
    float4 v[5], h[5];
    float ss = 0.0f;
#pragma unroll
    for (int j = 0; j < 5; j++) {
        v[j] = xr[lane + j * 32];
        ss += v[j].x * v[j].x + v[j].y * v[j].y + v[j].z * v[j].z + v[j].w * v[j].w;
    }
    ss = warp_red(ss, 0);
    float rinv = rsqrtf(ss / (float)HID + 1e-6f);
    float s2 = 0.0f;
#pragma unroll
    for (int j = 0; j < 5; j++) {
        float4 g4 = nw4[lane + j * 32];
        h[j].x = v[j].x * rinv * g4.x; h[j].y = v[j].y * rinv * g4.y;
        h[j].z = v[j].z * rinv * g4.z; h[j].w = v[j].w * rinv * g4.w;
        s2 += h[j].x * h[j].x + h[j].y * h[j].y + h[j].z * h[j].z + h[j].w * h[j].w;
    }
    s2 = warp_red(s2, 0);
    float rinv2 = rsqrtf(s2 / (float)HID + 1e-6f);

    const float* gains[3] = { qg, kg, vg };
    int8_t* dsts[3] = { g_xq_q, g_xq_k, g_xq_v };
    float* gmas[3] = { g_gamma_q, g_gamma_k, g_gamma_v };
#pragma unroll
    for (int which = 0; which < 3; which++) {
        const float4* g4p = (const float4*)gains[which];
        float4 hq[5];
        float gm = 0.0f;
#pragma unroll
        for (int j = 0; j < 5; j++) {
            float4 g4 = g4p[lane + j * 32];
            hq[j].x = h[j].x * rinv2 * g4.x; hq[j].y = h[j].y * rinv2 * g4.y;
            hq[j].z = h[j].z * rinv2 * g4.z; hq[j].w = h[j].w * rinv2 * g4.w;
            gm = fmaxf(gm, fmaxf(fmaxf(fabsf(hq[j].x), fabsf(hq[j].y)),
                                 fmaxf(fabsf(hq[j].z), fabsf(hq[j].w))));
        }
        gm = warp_red(gm, 1);
        gm = fmaxf(gm, 1e-10f);
        float sc = 127.0f / gm;
        char4* dst4 = (char4*)(dsts[which] + (size_t)t * HID);
#pragma unroll
        for (int j = 0; j < 5; j++) {
            char4 q;
            q.x = (int8_t)fminf(fmaxf(rintf(hq[j].x * sc), -128.0f), 127.0f);
            q.y = (int8_t)fminf(fmaxf(rintf(hq[j].y * sc), -128.0f), 127.0f);
            q.z = (int8_t)fminf(fmaxf(rintf(hq[j].z * sc), -128.0f), 127.0f);
            q.w = (int8_t)fminf(fmaxf(rintf(hq[j].w * sc), -128.0f), 127.0f);
            dst4[lane + j * 32] = q;
        }
        if (lane == 0) gmas[which][t] = gm;
    }
}

// ---------------- activation quant (O path) ----------------
__global__ __launch_bounds__(256) void act_quant_o(const float* __restrict__ og) {
    int warp = threadIdx.x >> 5, lane = threadIdx.x & 31;
    int t = blockIdx.x * 8 + warp;
    const float4* xr = (const float4*)(g_att + (size_t)t * HID);
    const float4* og4 = (const float4*)og;
    float4 v[5], hq[5];
    float ss = 0.0f;
#pragma unroll
    for (int j = 0; j < 5; j++) {
        v[j] = xr[lane + j * 32];
        ss += v[j].x * v[j].x + v[j].y * v[j].y + v[j].z * v[j].z + v[j].w * v[j].w;
    }
    ss = warp_red(ss, 0);
    float rinv = rsqrtf(ss / (float)HID + 1e-6f);
    float gm = 0.0f;
#pragma unroll
    for (int j = 0; j < 5; j++) {
        float4 g4 = og4[lane + j * 32];
        hq[j].x = v[j].x * rinv * g4.x; hq[j].y = v[j].y * rinv * g4.y;
        hq[j].z = v[j].z * rinv * g4.z; hq[j].w = v[j].w * rinv * g4.w;
        gm = fmaxf(gm, fmaxf(fmaxf(fabsf(hq[j].x), fabsf(hq[j].y)),
                             fmaxf(fabsf(hq[j].z), fabsf(hq[j].w))));
    }
    gm = warp_red(gm, 1);
    gm = fmaxf(gm, 1e-10f);
    float sc = 127.0f / gm;
    char4* dst4 = (char4*)(g_xq_o + (size_t)t * HID);
#pragma unroll
    for (int j = 0; j < 5; j++) {
        char4 q;
        q.x = (int8_t)fminf(fmaxf(rintf(hq[j].x * sc), -128.0f), 127.0f);
        q.y = (int8_t)fminf(fmaxf(rintf(hq[j].y * sc), -128.0f), 127.0f);
        q.z = (int8_t)fminf(fmaxf(rintf(hq[j].z * sc), -128.0f), 127.0f);
        q.w = (int8_t)fminf(fmaxf(rintf(hq[j].w * sc), -128.0f), 127.0f);
        dst4[lane + j * 32] = q;
    }
    if (lane == 0) g_gamma_o[t] = gm;
}

// ---------------- mma / async helpers ----------------
__device__ __forceinline__ uint32_t smem_u32(const void* p) {
    return (uint32_t)__cvta_generic_to_shared(p);
}
__device__ __forceinline__ void ldmx4(uint32_t* r, uint32_t addr) {
    asm volatile("ldmatrix.sync.aligned.m8n8.x4.shared.b16 {%0,%1,%2,%3}, [%4];\n"
                 : "=r"(r[0]), "=r"(r[1]), "=r"(r[2]), "=r"(r[3]) : "r"(addr));
}
__device__ __forceinline__ void ldmx4t(uint32_t* r, uint32_t addr) {
    asm volatile("ldmatrix.sync.aligned.m8n8.x4.trans.shared.b16 {%0,%1,%2,%3}, [%4];\n"
                 : "=r"(r[0]), "=r"(r[1]), "=r"(r[2]), "=r"(r[3]) : "r"(addr));
}
__device__ __forceinline__ void mma_f16(float* c, const uint32_t* a, uint32_t b0, uint32_t b1) {
    asm volatile("mma.sync.aligned.m16n8k16.row.col.f32.f16.f16.f32 "
                 "{%0,%1,%2,%3}, {%4,%5,%6,%7}, {%8,%9}, {%0,%1,%2,%3};\n"
                 : "+f"(c[0]), "+f"(c[1]), "+f"(c[2]), "+f"(c[3])
                 : "r"(a[0]), "r"(a[1]), "r"(a[2]), "r"(a[3]), "r"(b0), "r"(b1));
}
__device__ __forceinline__ void mma_s8(int* c, const uint32_t* a, uint32_t b0, uint32_t b1) {
    asm volatile("mma.sync.aligned.m16n8k32.row.col.s32.s8.s8.s32 "
                 "{%0,%1,%2,%3}, {%4,%5,%6,%7}, {%8,%9}, {%0,%1,%2,%3};\n"
                 : "+r"(c[0]), "+r"(c[1]), "+r"(c[2]), "+r"(c[3])
                 : "r"(a[0]), "r"(a[1]), "r"(a[2]), "r"(a[3]), "r"(b0), "r"(b1));
}
__device__ __forceinline__ void cp16(void* s, const void* g) {
    asm volatile("cp.async.cg.shared.global [%0], [%1], 16;\n"
                 :: "r"(smem_u32(s)), "l"(g));
}
__device__ __forceinline__ void cp_commit() {
    asm volatile("cp.async.commit_group;\n");
}
template <int N>
__device__ __forceinline__ void cp_wait() {
    asm volatile("cp.async.wait_group %0;\n" :: "n"(N));
}
__device__ __forceinline__ uint32_t pack_h2(__half x, __half y) {
    __half2 h = __halves2half2(x, y);
    return *(uint32_t*)&h;
}
__device__ __forceinline__ void split_h(float x, __half& hi, __half& lo) {
    hi = __float2half_rn(x);
    lo = __float2half_rn(x - __half2float(hi));
}

// ---------------- int8 TC GEMM, cp.async double-buffered ----------------------
#define GP 144
#define GSTAGE (128 * GP)
#define GEMM_SMEM (4 * GSTAGE)   // 73728 B

__device__ __forceinline__ void imma_tile(
    const int8_t* __restrict__ A, const int8_t* __restrict__ Bw,
    int t0, int n0, uint8_t* dsm, int acc[2][8][4]) {
    int8_t* As = (int8_t*)dsm;
    int8_t* Bs = (int8_t*)dsm + 2 * GSTAGE;
    int tid = threadIdx.x, warp = tid >> 5, lane = tid & 31;
    int wm = warp >> 1, wn = warp & 1;
#pragma unroll
    for (int mt = 0; mt < 2; mt++)
#pragma unroll
        for (int nt = 0; nt < 8; nt++)
#pragma unroll
            for (int i = 0; i < 4; i++) acc[mt][nt][i] = 0;

    int row = tid >> 1;
    int sh = (tid & 1) * 4;
#pragma unroll
    for (int c = 0; c <= 5; c++) {
        if (c < 5) {
            int st = (c & 1) * GSTAGE;
#pragma unroll
            for (int s = 0; s < 4; s++) {
                int seg = sh + s;
                cp16(&As[st + row * GP + seg * 16],
                     &A[(size_t)(t0 + row) * HID + c * 128 + seg * 16]);
                cp16(&Bs[st + row * GP + seg * 16],
                     &Bw[(size_t)(n0 + row) * HID + c * 128 + seg * 16]);
            }
            cp_commit();
        }
        if (c == 0) continue;
        int cc = c - 1;
        if (c < 5) cp_wait<1>(); else cp_wait<0>();
        __syncthreads();
        int st = (cc & 1) * GSTAGE;
#pragma unroll
        for (int ks = 0; ks < 4; ks++) {
            uint32_t af[2][4];
#pragma unroll
            for (int mt = 0; mt < 2; mt++)
                ldmx4(af[mt], smem_u32(&As[st + (wm * 32 + mt * 16 + (lane & 15)) * GP +
                                            ks * 32 + (lane >> 4) * 16]));
#pragma unroll
            for (int np = 0; np < 4; np++) {
                uint32_t bf[4];
                ldmx4(bf, smem_u32(&Bs[st + (wn * 64 + np * 16 + (lane & 15)) * GP +
                                        ks * 32 + (lane >> 4) * 16]));
#pragma unroll
                for (int mt = 0; mt < 2; mt++) {
                    mma_s8(acc[mt][np * 2],     af[mt], bf[0], bf[2]);
                    mma_s8(acc[mt][np * 2 + 1], af[mt], bf[1], bf[3]);
                }
            }
        }
        __syncthreads();
    }
}

// epilogue helper: rope + fp16 hi/lo split write
__device__ __forceinline__ void write_qkv_pair(
    float v0, float v1, int r, int n, int nheads, int rope,
    __half* __restrict__ hob, __half* __restrict__ lob) {
    int head = n >> 6, d = n & 63;
    int bI = r >> 9, l = r & 511;
    if (rope) {
        int p = d >> 1;
        float c0 = g_cos[l * 32 + p], sn0 = g_sin[l * 32 + p];
        float t0f = v0 * c0 - v1 * sn0, t1f = v1 * c0 + v0 * sn0;
        v0 = t0f; v1 = t1f;
    }
    size_t i0 = (((size_t)bI * nheads + head) * SEQ + l) * HD + d;
    __half h0, h1, e0, e1;
    split_h(v0, h0, e0); split_h(v1, h1, e1);
    *(__half2*)&hob[i0] = __halves2half2(h0, h1);
    *(__half2*)&lob[i0] = __halves2half2(e0, e1);
}

// ---------------- fused QKV GEMM (pure IMMA) ----------------------------------
// blocks [0,640): Q; [640,768): K; [768,896): V
__global__ __launch_bounds__(256) void gemm_qkv() {
    extern __shared__ uint8_t dsm[];
    int bid = blockIdx.x;
    int path, bx, by;
    if (bid < 640)      { path = 0; bx = bid & 127; by = bid >> 7; }
    else if (bid < 768) { path = 1; bx = bid - 640; by = 0; }
    else                { path = 2; bx = bid - 768; by = 0; }
    const int8_t* A  = path == 0 ? g_xq_q : path == 1 ? g_xq_k : g_xq_v;
    const int8_t* Bw = path == 0 ? g_wq_q : path == 1 ? g_wq_k : g_wq_v;
    const float* gamma = path == 0 ? g_gamma_q : path == 1 ? g_gamma_k : g_gamma_v;
    __half* hob = path == 0 ? g_qh : path == 1 ? g_kh : g_vh;
    __half* lob = path == 0 ? g_ql : path == 1 ? g_kl : g_vl;
    int nheads = path == 0 ? NQH : NKVH;
    int rope   = path == 2 ? 0 : 1;
    float oscale = path == 0 ? 0.125f : 1.0f;
    int t0 = bx * 128, n0 = by * 128;
    int tid = threadIdx.x;
    float alphab = g_alpha[path] * (1.0f / 127.0f) * oscale;

    int acc[2][8][4];
    imma_tile(A, Bw, t0, n0, dsm, acc);
    int warp = tid >> 5, lane = tid & 31;
    int wm = warp >> 1, wn = warp & 1;
#pragma unroll
    for (int mt = 0; mt < 2; mt++) {
        int r0 = t0 + wm * 32 + mt * 16 + (lane >> 2);
        int r1 = r0 + 8;
        float s0 = alphab * gamma[r0];
        float s1 = alphab * gamma[r1];
#pragma unroll
        for (int nt = 0; nt < 8; nt++) {
            int n = n0 + wn * 64 + nt * 8 + (lane & 3) * 2;
            write_qkv_pair((float)acc[mt][nt][0] * s0, (float)acc[mt][nt][1] * s0,
                           r0, n, nheads, rope, hob, lob);
            write_qkv_pair((float)acc[mt][nt][2] * s1, (float)acc[mt][nt][3] * s1,
                           r1, n, nheads, rope, hob, lob);
        }
    }
}

// ---------------- O-proj GEMM (pure IMMA, float out + residual) ---------------
__global__ __launch_bounds__(256) void gemm_o(
    float* __restrict__ outf, const float* __restrict__ resid) {
    extern __shared__ uint8_t dsm[];
    int t0 = blockIdx.x * 128, n0 = blockIdx.y * 128;
    int tid = threadIdx.x;
    float alphab = g_alpha[3] * (1.0f / 127.0f);

    int acc[2][8][4];
    imma_tile(g_xq_o, g_wq_o, t0, n0, dsm, acc);
    int warp = tid >> 5, lane = tid & 31;
    int wm = warp >> 1, wn = warp & 1;
#pragma unroll
    for (int mt = 0; mt < 2; mt++) {
        int r0 = t0 + wm * 32 + mt * 16 + (lane >> 2);
        int r1 = r0 + 8;
        float s0 = alphab * g_gamma_o[r0];
        float s1 = alphab * g_gamma_o[r1];
#pragma unroll
        for (int nt = 0; nt < 8; nt++) {
            int n = n0 + wn * 64 + nt * 8 + (lane & 3) * 2;
            const float* rr0 = resid + (size_t)r0 * HID + n;
            const float* rr1 = resid + (size_t)r1 * HID + n;
            *(float2*)&outf[(size_t)r0 * HID + n] =
                make_float2((float)acc[mt][nt][0] * s0 + rr0[0],
                            (float)acc[mt][nt][1] * s0 + rr0[1]);
            *(float2*)&outf[(size_t)r1 * HID + n] =
                make_float2((float)acc[mt][nt][2] * s1 + rr1[0],
                            (float)acc[mt][nt][3] * s1 + rr1[1]);
        }
    }
}

// ---------------- attention: flash, split-fp16 mma, 2 blocks/SM ----------------
#define SPITCH 72
#define ATTN_SMEM (36864 * 2)   // 73728 B
__global__ __launch_bounds__(256, 2) void attn_mma(float* __restrict__ out) {
    extern __shared__ __half ASM[];

    int tid = threadIdx.x;
    int warp = tid >> 5, lane = tid & 31;
    int qt = blockIdx.x;
    int bh = blockIdx.y;
    int b = bh / NQH, h = bh % NQH;
    int kvh = h / (NQH / NKVH);

    size_t qoff = ((size_t)(b * NQH + h) * SEQ + qt * 128) * HD;
    size_t kvoff = (size_t)(b * NKVH + kvh) * SEQ * HD;
    const __half* gbuf[4] = { g_kh + kvoff, g_kl + kvoff, g_vh + kvoff, g_vl + kvoff };

    __half* Qh = ASM;
    __half* Ql = ASM + 9216;
#pragma unroll
    for (int i = 0; i < 4; i++) {
        int slot = tid + i * 256;
        int r = slot >> 3, seg = slot & 7;
        *(float4*)&Qh[r * SPITCH + seg * 8] = *(const float4*)&g_qh[qoff + r * 64 + seg * 8];
        *(float4*)&Ql[r * SPITCH + seg * 8] = *(const float4*)&g_ql[qoff + r * 64 + seg * 8];
    }
    __syncthreads();

    {
        __half* sb = ASM + 18432;
#pragma unroll
        for (int i = 0; i < 8; i++) {
            int slot = tid + i * 256;
            int bufi = slot >> 9, r = (slot >> 3) & 63, seg = slot & 7;
            cp16(&sb[bufi * 4608 + r * SPITCH + seg * 8], &gbuf[bufi][r * 64 + seg * 8]);
        }
        cp_commit();
    }

    uint32_t qah[4][4], qal[4][4];
    int m0 = warp * 16;
#pragma unroll
    for (int kc = 0; kc < 4; kc++) {
        int r = m0 + (lane & 15), c = kc * 16 + (lane >> 4) * 8;
        ldmx4(qah[kc], smem_u32(&Qh[r * SPITCH + c]));
        ldmx4(qal[kc], smem_u32(&Ql[r * SPITCH + c]));
    }
    __syncthreads();

    float oacc[8][4];
#pragma unroll
    for (int nt = 0; nt < 8; nt++)
#pragma unroll
        for (int i = 0; i < 4; i++) oacc[nt][i] = 0.0f;
    float mrow0 = -1e30f, mrow1 = -1e30f, lrow0 = 0.0f, lrow1 = 0.0f;

    for (int kt = 0; kt < 8; kt++) {
        if (kt < 7) {
            __half* sb = ASM + (kt & 1) * 18432;
#pragma unroll
            for (int i = 0; i < 8; i++) {
                int slot = tid + i * 256;
                int bufi = slot >> 9, r = (slot >> 3) & 63, seg = slot & 7;
                cp16(&sb[bufi * 4608 + r * SPITCH + seg * 8],
                     &gbuf[bufi][((kt + 1) * 64 + r) * 64 + seg * 8]);
            }
            cp_commit();
            cp_wait<1>();
        } else {
            cp_wait<0>();
        }
        __syncthreads();
        __half* sb = ASM + ((kt + 1) & 1) * 18432;
        __half* Khs = sb;
        __half* Kls = sb + 4608;
        __half* Vhs = sb + 9216;
        __half* Vls = sb + 13824;

        float sacc[8][4];
#pragma unroll
        for (int nt = 0; nt < 8; nt++)
#pragma unroll
            for (int i = 0; i < 4; i++) sacc[nt][i] = 0.0f;
        int g = lane >> 3;
        int n_off = (g >= 2) ? 8 : 0, k_off = (g & 1) * 8;
#pragma unroll
        for (int nt2 = 0; nt2 < 4; nt2++) {
#pragma unroll
            for (int kc = 0; kc < 4; kc++) {
                uint32_t kbh[4], kbl[4];
                int r = nt2 * 16 + n_off + (lane & 7), c = kc * 16 + k_off;
                ldmx4(kbh, smem_u32(&Khs[r * SPITCH + c]));
                ldmx4(kbl, smem_u32(&Kls[r * SPITCH + c]));
                mma_f16(sacc[nt2 * 2],     qah[kc], kbh[0], kbh[1]);
                mma_f16(sacc[nt2 * 2],     qah[kc], kbl[0], kbl[1]);
                mma_f16(sacc[nt2 * 2],     qal[kc], kbh[0], kbh[1]);
                mma_f16(sacc[nt2 * 2 + 1], qah[kc], kbh[2], kbh[3]);
                mma_f16(sacc[nt2 * 2 + 1], qah[kc], kbl[2], kbl[3]);
                mma_f16(sacc[nt2 * 2 + 1], qal[kc], kbh[2], kbh[3]);
            }
        }

        float mx0 = -1e30f, mx1 = -1e30f;
#pragma unroll
        for (int nt = 0; nt < 8; nt++) {
            mx0 = fmaxf(mx0, fmaxf(sacc[nt][0], sacc[nt][1]));
            mx1 = fmaxf(mx1, fmaxf(sacc[nt][2], sacc[nt][3]));
        }
        mx0 = fmaxf(mx0, __shfl_xor_sync(0xffffffffu, mx0, 1));
        mx0 = fmaxf(mx0, __shfl_xor_sync(0xffffffffu, mx0, 2));
        mx1 = fmaxf(mx1, __shfl_xor_sync(0xffffffffu, mx1, 1));
        mx1 = fmaxf(mx1, __shfl_xor_sync(0xffffffffu, mx1, 2));
        float mn0 = fmaxf(mrow0, mx0), mn1 = fmaxf(mrow1, mx1);
        float e0 = __expf(mrow0 - mn0), e1 = __expf(mrow1 - mn1);
        mrow0 = mn0; mrow1 = mn1;

        float sum0 = 0.0f, sum1 = 0.0f;
        uint32_t pah[4][4], pal[4][4];
#pragma unroll
        for (int kc2 = 0; kc2 < 4; kc2++) {
            int nta = kc2 * 2, ntb = nta + 1;
            float p[8];
            p[0] = __expf(sacc[nta][0] - mn0); p[1] = __expf(sacc[nta][1] - mn0);
            p[2] = __expf(sacc[nta][2] - mn1); p[3] = __expf(sacc[nta][3] - mn1);
            p[4] = __expf(sacc[ntb][0] - mn0); p[5] = __expf(sacc[ntb][1] - mn0);
            p[6] = __expf(sacc[ntb][2] - mn1); p[7] = __expf(sacc[ntb][3] - mn1);
            __half ph[8], pl[8];
#pragma unroll
            for (int i = 0; i < 8; i++) split_h(p[i], ph[i], pl[i]);
            sum0 += p[0] + p[1] + p[4] + p[5];
            sum1 += p[2] + p[3] + p[6] + p[7];
            pah[kc2][0] = pack_h2(ph[0], ph[1]); pal[kc2][0] = pack_h2(pl[0], pl[1]);
            pah[kc2][1] = pack_h2(ph[2], ph[3]); pal[kc2][1] = pack_h2(pl[2], pl[3]);
            pah[kc2][2] = pack_h2(ph[4], ph[5]); pal[kc2][2] = pack_h2(pl[4], pl[5]);
            pah[kc2][3] = pack_h2(ph[6], ph[7]); pal[kc2][3] = pack_h2(pl[6], pl[7]);
        }
        sum0 += __shfl_xor_sync(0xffffffffu, sum0, 1);
        sum0 += __shfl_xor_sync(0xffffffffu, sum0, 2);
        sum1 += __shfl_xor_sync(0xffffffffu, sum1, 1);
        sum1 += __shfl_xor_sync(0xffffffffu, sum1, 2);
        lrow0 = lrow0 * e0 + sum0;
        lrow1 = lrow1 * e1 + sum1;

#pragma unroll
        for (int nt = 0; nt < 8; nt++) {
            oacc[nt][0] *= e0; oacc[nt][1] *= e0;
            oacc[nt][2] *= e1; oacc[nt][3] *= e1;
        }

#pragma unroll
        for (int kc2 = 0; kc2 < 4; kc2++) {
#pragma unroll
            for (int nt2 = 0; nt2 < 4; nt2++) {
                uint32_t vbh[4], vbl[4];
                int r = kc2 * 16 + (g & 1) * 8 + (lane & 7);
                int c = nt2 * 16 + ((g >= 2) ? 8 : 0);
                ldmx4t(vbh, smem_u32(&Vhs[r * SPITCH + c]));
                ldmx4t(vbl, smem_u32(&Vls[r * SPITCH + c]));
                mma_f16(oacc[nt2 * 2],     pah[kc2], vbh[0], vbh[1]);
                mma_f16(oacc[nt2 * 2],     pah[kc2], vbl[0], vbl[1]);
                mma_f16(oacc[nt2 * 2],     pal[kc2], vbh[0], vbh[1]);
                mma_f16(oacc[nt2 * 2 + 1], pah[kc2], vbh[2], vbh[3]);
                mma_f16(oacc[nt2 * 2 + 1], pah[kc2], vbl[2], vbl[3]);
                mma_f16(oacc[nt2 * 2 + 1], pal[kc2], vbh[2], vbh[3]);
            }
        }
        __syncthreads();
    }

    float inv0 = 1.0f / lrow0, inv1 = 1.0f / lrow1;
    int r0 = qt * 128 + m0 + (lane >> 2);
    int r1 = r0 + 8;
#pragma unroll
    for (int nt = 0; nt < 8; nt++) {
        int col = h * HD + nt * 8 + (lane & 3) * 2;
        float2 v0 = make_float2(oacc[nt][0] * inv0, oacc[nt][1] * inv0);
        float2 v1 = make_float2(oacc[nt][2] * inv1, oacc[nt][3] * inv1);
        *(float2*)&out[((size_t)b * SEQ + r0) * HID + col] = v0;
        *(float2*)&out[((size_t)b * SEQ + r1) * HID + col] = v1;
    }
}

// ---------------- launch ----------------
extern "C" void kernel_launch(void* const* d_in, const int* in_sizes, int n_in,
                              void* d_out, int out_size) {
    const float* x      = (const float*)d_in[0];
    const float* norm_w = (const float*)d_in[1];
    const float* q_w    = (const float*)d_in[2];
    const float* q_g    = (const float*)d_in[3];
    const float* k_w    = (const float*)d_in[4];
    const float* k_g    = (const float*)d_in[5];
    const float* v_w    = (const float*)d_in[6];
    const float* v_g    = (const float*)d_in[7];
    const float* o_w    = (const float*)d_in[8];
    const float* o_g    = (const float*)d_in[9];
    float* out = (float*)d_out;

    void* p_att;
    cudaGetSymbolAddress(&p_att, g_att);

    cudaFuncSetAttribute(gemm_qkv, cudaFuncAttributeMaxDynamicSharedMemorySize, GEMM_SMEM);
    cudaFuncSetAttribute(gemm_o, cudaFuncAttributeMaxDynamicSharedMemorySize, GEMM_SMEM);
    cudaFuncSetAttribute(attn_mma, cudaFuncAttributeMaxDynamicSharedMemorySize, ATTN_SMEM);

    // 1. weight alphas + rope tables (fused, 1024-thread blocks)
    prep_all<<<68, 1024>>>(q_w, k_w, v_w, o_w);

    // 2. weight ternary quant
    wquant_all<<<(2 * HID * HID + 2 * KVDIM * HID + 255) / 256, 256>>>(q_w, k_w, v_w, o_w);

    // 3. activation double-rmsnorm + int8 quant
    act_quant_qkv<<<T_TOKENS / 8, 256>>>(x, norm_w, q_g, k_g, v_g);

    // 4. fused QKV GEMMs (pure IMMA; rope + hi/lo split epilogue)
    gemm_qkv<<<896, 256, GEMM_SMEM>>>();

    // 5. attention (2 blocks/SM via launch_bounds)
    attn_mma<<<dim3(SEQ / 128, BATCH * NQH), 256, ATTN_SMEM>>>((float*)p_att);

    // 6. O-proj quant + GEMM + residual
    act_quant_o<<<T_TOKENS / 8, 256>>>(o_g);
    gemm_o<<<dim3(128, 5), 256, GEMM_SMEM>>>(out, x);
}

// round 16
// speedup vs baseline: 1.1772x; 1.0744x over previous
#include <cuda_runtime.h>
#include <cuda_fp16.h>
#include <math.h>
#include <stdint.h>

#define T_TOKENS 16384
#define HID      640
#define NQH      10
#define NKVH     2
#define HD       64
#define SEQ      512
#define BATCH    32
#define KVDIM    128

// ---------------- scratch ----------------
__device__ __align__(16) int8_t g_xq_q[T_TOKENS * HID];
__device__ __align__(16) int8_t g_xq_k[T_TOKENS * HID];
__device__ __align__(16) int8_t g_xq_v[T_TOKENS * HID];
__device__ __align__(16) int8_t g_xq_o[T_TOKENS * HID];
__device__ __align__(16) int8_t g_wq_q[HID * HID];
__device__ __align__(16) int8_t g_wq_k[KVDIM * HID];
__device__ __align__(16) int8_t g_wq_v[KVDIM * HID];
__device__ __align__(16) int8_t g_wq_o[HID * HID];
__device__ float g_gamma_q[T_TOKENS];
__device__ float g_gamma_k[T_TOKENS];
__device__ float g_gamma_v[T_TOKENS];
__device__ float g_gamma_o[T_TOKENS];
__device__ float g_alpha[4];
__device__ __align__(16) __half g_qh[BATCH * NQH * SEQ * HD];
__device__ __align__(16) __half g_ql[BATCH * NQH * SEQ * HD];
__device__ __align__(16) __half g_kh[BATCH * NKVH * SEQ * HD];
__device__ __align__(16) __half g_kl[BATCH * NKVH * SEQ * HD];
__device__ __align__(16) __half g_vh[BATCH * NKVH * SEQ * HD];
__device__ __align__(16) __half g_vl[BATCH * NKVH * SEQ * HD];
__device__ float g_att[T_TOKENS * HID];
__device__ float g_cos[SEQ * 32];
__device__ float g_sin[SEQ * 32];

// ---------------- reduction helpers ----------------
__device__ __forceinline__ float warp_red(float v, int op) {
#pragma unroll
    for (int o = 16; o; o >>= 1) {
        float t = __shfl_xor_sync(0xffffffffu, v, o);
        v = op ? fmaxf(v, t) : v + t;
    }
    return v;
}
__device__ __forceinline__ float block_reduce(float v, int op, float* sm, int nwarps) {
    int lane = threadIdx.x & 31, w = threadIdx.x >> 5;
    v = warp_red(v, op);
    if (!lane) sm[w] = v;
    __syncthreads();
    if (w == 0) {
        v = (lane < nwarps) ? sm[lane] : (op ? -INFINITY : 0.0f);
        v = warp_red(v, op);
        if (!lane) sm[0] = v;
    }
    __syncthreads();
    v = sm[0];
    __syncthreads();
    return v;
}

// ---------------- prep: weight alpha (blocks 0-3) + rope tables ----------------
__global__ __launch_bounds__(1024) void prep_all(
    const float* __restrict__ qw, const float* __restrict__ kw,
    const float* __restrict__ vw, const float* __restrict__ ow) {
    if (blockIdx.x < 4) {
        __shared__ float sm[32];
        int which = blockIdx.x;
        const float* w = which == 0 ? qw : which == 1 ? kw : which == 2 ? vw : ow;
        int n = (which == 1 || which == 2) ? (KVDIM * HID) : (HID * HID);
        float s = 0.0f;
        for (int i = threadIdx.x; i < n; i += 1024) s += fabsf(w[i]);
        s = block_reduce(s, 0, sm, 32);
        if (threadIdx.x == 0) g_alpha[which] = fmaxf(s / (float)n, 1e-10f);
    } else {
        int idx = (blockIdx.x - 4) * 1024 + threadIdx.x;
        if (idx >= SEQ * 32) return;
        int l = idx >> 5, p = idx & 31;
        double freq = exp2(-(double)p * (18.93156856932417 / 32.0));  // 500000^(-p/32)
        double a = (double)l * freq;
        const double TWO_PI = 6.283185307179586476925287;
        double r = a - floor(a * (1.0 / TWO_PI)) * TWO_PI;
        float rf = (float)r;
        g_cos[idx] = cosf(rf);
        g_sin[idx] = sinf(rf);
    }
}

// ---------------- weight ternary quant ----------------
__global__ void wquant_all(const float* __restrict__ qw, const float* __restrict__ kw,
                           const float* __restrict__ vw, const float* __restrict__ ow) {
    int idx = blockIdx.x * blockDim.x + threadIdx.x;
    const float* w; int8_t* dst; int off; int which;
    const int nQ = HID * HID, nK = KVDIM * HID;
    if (idx < nQ)                       { which = 0; w = qw; dst = g_wq_q; off = idx; }
    else if (idx < nQ + nK)             { which = 1; w = kw; dst = g_wq_k; off = idx - nQ; }
    else if (idx < nQ + 2 * nK)         { which = 2; w = vw; dst = g_wq_v; off = idx - nQ - nK; }
    else if (idx < 2 * nQ + 2 * nK)     { which = 3; w = ow; dst = g_wq_o; off = idx - nQ - 2 * nK; }
    else return;
    float a = g_alpha[which];
    float q = rintf(w[off] / a);
    q = fminf(fmaxf(q, -1.0f), 1.0f);
    dst[off] = (int8_t)q;
}

// ---------------- activation quant, warp-per-token (QKV) ----------------
__global__ __launch_bounds__(256) void act_quant_qkv(
    const float* __restrict__ x, const float* __restrict__ nw,
    const float* __restrict__ qg, const float* __restrict__ kg, const float* __restrict__ vg) {
    int warp = threadIdx.x >> 5, lane = threadIdx.x & 31;
    int t = blockIdx.x * 8 + warp;
    const float4* xr = (const float4*)(x + (size_t)t * HID);
    const float4* nw4 = (const float4*)nw;
    float4 v[5], h[5];
    float ss = 0.0f;
#pragma unroll
    for (int j = 0; j < 5; j++) {
        v[j] = xr[lane + j * 32];
        ss += v[j].x * v[j].x + v[j].y * v[j].y + v[j].z * v[j].z + v[j].w * v[j].w;
    }
    ss = warp_red(ss, 0);
    float rinv = rsqrtf(ss / (float)HID + 1e-6f);
    float s2 = 0.0f;
#pragma unroll
    for (int j = 0; j < 5; j++) {
        float4 g4 = nw4[lane + j * 32];
        h[j].x = v[j].x * rinv * g4.x; h[j].y = v[j].y * rinv * g4.y;
        h[j].z = v[j].z * rinv * g4.z; h[j].w = v[j].w * rinv * g4.w;
        s2 += h[j].x * h[j].x + h[j].y * h[j].y + h[j].z * h[j].z + h[j].w * h[j].w;
    }
    s2 = warp_red(s2, 0);
    float rinv2 = rsqrtf(s2 / (float)HID + 1e-6f);

    const float* gains[3] = { qg, kg, vg };
    int8_t* dsts[3] = { g_xq_q, g_xq_k, g_xq_v };
    float* gmas[3] = { g_gamma_q, g_gamma_k, g_gamma_v };
#pragma unroll
    for (int which = 0; which < 3; which++) {
        const float4* g4p = (const float4*)gains[which];
        float4 hq[5];
        float gm = 0.0f;
#pragma unroll
        for (int j = 0; j < 5; j++) {
            float4 g4 = g4p[lane + j * 32];
            hq[j].x = h[j].x * rinv2 * g4.x; hq[j].y = h[j].y * rinv2 * g4.y;
            hq[j].z = h[j].z * rinv2 * g4.z; hq[j].w = h[j].w * rinv2 * g4.w;
            gm = fmaxf(gm, fmaxf(fmaxf(fabsf(hq[j].x), fabsf(hq[j].y)),
                                 fmaxf(fabsf(hq[j].z), fabsf(hq[j].w))));
        }
        gm = warp_red(gm, 1);
        gm = fmaxf(gm, 1e-10f);
        float sc = 127.0f / gm;
        char4* dst4 = (char4*)(dsts[which] + (size_t)t * HID);
#pragma unroll
        for (int j = 0; j < 5; j++) {
            char4 q;
            q.x = (int8_t)fminf(fmaxf(rintf(hq[j].x * sc), -128.0f), 127.0f);
            q.y = (int8_t)fminf(fmaxf(rintf(hq[j].y * sc), -128.0f), 127.0f);
            q.z = (int8_t)fminf(fmaxf(rintf(hq[j].z * sc), -128.0f), 127.0f);
            q.w = (int8_t)fminf(fmaxf(rintf(hq[j].w * sc), -128.0f), 127.0f);
            dst4[lane + j * 32] = q;
        }
        if (lane == 0) gmas[which][t] = gm;
    }
}

// ---------------- activation quant (O path) ----------------
__global__ __launch_bounds__(256) void act_quant_o(const float* __restrict__ og) {
    int warp = threadIdx.x >> 5, lane = threadIdx.x & 31;
    int t = blockIdx.x * 8 + warp;
    const float4* xr = (const float4*)(g_att + (size_t)t * HID);
    const float4* og4 = (const float4*)og;
    float4 v[5], hq[5];
    float ss = 0.0f;
#pragma unroll
    for (int j = 0; j < 5; j++) {
        v[j] = xr[lane + j * 32];
        ss += v[j].x * v[j].x + v[j].y * v[j].y + v[j].z * v[j].z + v[j].w * v[j].w;
    }
    ss = warp_red(ss, 0);
    float rinv = rsqrtf(ss / (float)HID + 1e-6f);
    float gm = 0.0f;
#pragma unroll
    for (int j = 0; j < 5; j++) {
        float4 g4 = og4[lane + j * 32];
        hq[j].x = v[j].x * rinv * g4.x; hq[j].y = v[j].y * rinv * g4.y;
        hq[j].z = v[j].z * rinv * g4.z; hq[j].w = v[j].w * rinv * g4.w;
        gm = fmaxf(gm, fmaxf(fmaxf(fabsf(hq[j].x), fabsf(hq[j].y)),
                             fmaxf(fabsf(hq[j].z), fabsf(hq[j].w))));
    }
    gm = warp_red(gm, 1);
    gm = fmaxf(gm, 1e-10f);
    float sc = 127.0f / gm;
    char4* dst4 = (char4*)(g_xq_o + (size_t)t * HID);
#pragma unroll
    for (int j = 0; j < 5; j++) {
        char4 q;
        q.x = (int8_t)fminf(fmaxf(rintf(hq[j].x * sc), -128.0f), 127.0f);
        q.y = (int8_t)fminf(fmaxf(rintf(hq[j].y * sc), -128.0f), 127.0f);
        q.z = (int8_t)fminf(fmaxf(rintf(hq[j].z * sc), -128.0f), 127.0f);
        q.w = (int8_t)fminf(fmaxf(rintf(hq[j].w * sc), -128.0f), 127.0f);
        dst4[lane + j * 32] = q;
    }
    if (lane == 0) g_gamma_o[t] = gm;
}

// ---------------- mma / async helpers ----------------
__device__ __forceinline__ uint32_t smem_u32(const void* p) {
    return (uint32_t)__cvta_generic_to_shared(p);
}
__device__ __forceinline__ void ldmx4(uint32_t* r, uint32_t addr) {
    asm volatile("ldmatrix.sync.aligned.m8n8.x4.shared.b16 {%0,%1,%2,%3}, [%4];\n"
                 : "=r"(r[0]), "=r"(r[1]), "=r"(r[2]), "=r"(r[3]) : "r"(addr));
}
__device__ __forceinline__ void ldmx4t(uint32_t* r, uint32_t addr) {
    asm volatile("ldmatrix.sync.aligned.m8n8.x4.trans.shared.b16 {%0,%1,%2,%3}, [%4];\n"
                 : "=r"(r[0]), "=r"(r[1]), "=r"(r[2]), "=r"(r[3]) : "r"(addr));
}
__device__ __forceinline__ void mma_f16(float* c, const uint32_t* a, uint32_t b0, uint32_t b1) {
    asm volatile("mma.sync.aligned.m16n8k16.row.col.f32.f16.f16.f32 "
                 "{%0,%1,%2,%3}, {%4,%5,%6,%7}, {%8,%9}, {%0,%1,%2,%3};\n"
                 : "+f"(c[0]), "+f"(c[1]), "+f"(c[2]), "+f"(c[3])
                 : "r"(a[0]), "r"(a[1]), "r"(a[2]), "r"(a[3]), "r"(b0), "r"(b1));
}
__device__ __forceinline__ void mma_s8(int* c, const uint32_t* a, uint32_t b0, uint32_t b1) {
    asm volatile("mma.sync.aligned.m16n8k32.row.col.s32.s8.s8.s32 "
                 "{%0,%1,%2,%3}, {%4,%5,%6,%7}, {%8,%9}, {%0,%1,%2,%3};\n"
                 : "+r"(c[0]), "+r"(c[1]), "+r"(c[2]), "+r"(c[3])
                 : "r"(a[0]), "r"(a[1]), "r"(a[2]), "r"(a[3]), "r"(b0), "r"(b1));
}
__device__ __forceinline__ void cp16(void* s, const void* g) {
    asm volatile("cp.async.cg.shared.global [%0], [%1], 16;\n"
                 :: "r"(smem_u32(s)), "l"(g));
}
__device__ __forceinline__ void cp_commit() {
    asm volatile("cp.async.commit_group;\n");
}
template <int N>
__device__ __forceinline__ void cp_wait() {
    asm volatile("cp.async.wait_group %0;\n" :: "n"(N));
}
__device__ __forceinline__ uint32_t pack_h2(__half x, __half y) {
    __half2 h = __halves2half2(x, y);
    return *(uint32_t*)&h;
}
__device__ __forceinline__ void split_h(float x, __half& hi, __half& lo) {
    hi = __float2half_rn(x);
    lo = __float2half_rn(x - __half2float(hi));
}

// ---------------- int8 TC GEMM, cp.async double-buffered ----------------------
#define GP 144
#define GSTAGE (128 * GP)
#define GEMM_SMEM (4 * GSTAGE)   // 73728 B

__device__ __forceinline__ void imma_tile(
    const int8_t* __restrict__ A, const int8_t* __restrict__ Bw,
    int t0, int n0, uint8_t* dsm, int acc[2][8][4]) {
    int8_t* As = (int8_t*)dsm;
    int8_t* Bs = (int8_t*)dsm + 2 * GSTAGE;
    int tid = threadIdx.x, warp = tid >> 5, lane = tid & 31;
    int wm = warp >> 1, wn = warp & 1;
#pragma unroll
    for (int mt = 0; mt < 2; mt++)
#pragma unroll
        for (int nt = 0; nt < 8; nt++)
#pragma unroll
            for (int i = 0; i < 4; i++) acc[mt][nt][i] = 0;

    int row = tid >> 1;
    int sh = (tid & 1) * 4;
#pragma unroll
    for (int c = 0; c <= 5; c++) {
        if (c < 5) {
            int st = (c & 1) * GSTAGE;
#pragma unroll
            for (int s = 0; s < 4; s++) {
                int seg = sh + s;
                cp16(&As[st + row * GP + seg * 16],
                     &A[(size_t)(t0 + row) * HID + c * 128 + seg * 16]);
                cp16(&Bs[st + row * GP + seg * 16],
                     &Bw[(size_t)(n0 + row) * HID + c * 128 + seg * 16]);
            }
            cp_commit();
        }
        if (c == 0) continue;
        int cc = c - 1;
        if (c < 5) cp_wait<1>(); else cp_wait<0>();
        __syncthreads();
        int st = (cc & 1) * GSTAGE;
#pragma unroll
        for (int ks = 0; ks < 4; ks++) {
            uint32_t af[2][4];
#pragma unroll
            for (int mt = 0; mt < 2; mt++)
                ldmx4(af[mt], smem_u32(&As[st + (wm * 32 + mt * 16 + (lane & 15)) * GP +
                                            ks * 32 + (lane >> 4) * 16]));
#pragma unroll
            for (int np = 0; np < 4; np++) {
                uint32_t bf[4];
                ldmx4(bf, smem_u32(&Bs[st + (wn * 64 + np * 16 + (lane & 15)) * GP +
                                        ks * 32 + (lane >> 4) * 16]));
#pragma unroll
                for (int mt = 0; mt < 2; mt++) {
                    mma_s8(acc[mt][np * 2],     af[mt], bf[0], bf[2]);
                    mma_s8(acc[mt][np * 2 + 1], af[mt], bf[1], bf[3]);
                }
            }
        }
        __syncthreads();
    }
}

// epilogue helper: rope + fp16 hi/lo split write
__device__ __forceinline__ void write_qkv_pair(
    float v0, float v1, int r, int n, int nheads, int rope,
    __half* __restrict__ hob, __half* __restrict__ lob) {
    int head = n >> 6, d = n & 63;
    int bI = r >> 9, l = r & 511;
    if (rope) {
        int p = d >> 1;
        float c0 = g_cos[l * 32 + p], sn0 = g_sin[l * 32 + p];
        float t0f = v0 * c0 - v1 * sn0, t1f = v1 * c0 + v0 * sn0;
        v0 = t0f; v1 = t1f;
    }
    size_t i0 = (((size_t)bI * nheads + head) * SEQ + l) * HD + d;
    __half h0, h1, e0, e1;
    split_h(v0, h0, e0); split_h(v1, h1, e1);
    *(__half2*)&hob[i0] = __halves2half2(h0, h1);
    *(__half2*)&lob[i0] = __halves2half2(e0, e1);
}

// ---------------- fused QKV GEMM (pure IMMA, 2 blocks/SM) ---------------------
// blocks [0,640): Q; [640,768): K; [768,896): V
__global__ __launch_bounds__(256, 2) void gemm_qkv() {
    extern __shared__ uint8_t dsm[];
    int bid = blockIdx.x;
    int path, bx, by;
    if (bid < 640)      { path = 0; bx = bid & 127; by = bid >> 7; }
    else if (bid < 768) { path = 1; bx = bid - 640; by = 0; }
    else                { path = 2; bx = bid - 768; by = 0; }
    const int8_t* A  = path == 0 ? g_xq_q : path == 1 ? g_xq_k : g_xq_v;
    const int8_t* Bw = path == 0 ? g_wq_q : path == 1 ? g_wq_k : g_wq_v;
    const float* gamma = path == 0 ? g_gamma_q : path == 1 ? g_gamma_k : g_gamma_v;
    __half* hob = path == 0 ? g_qh : path == 1 ? g_kh : g_vh;
    __half* lob = path == 0 ? g_ql : path == 1 ? g_kl : g_vl;
    int nheads = path == 0 ? NQH : NKVH;
    int rope   = path == 2 ? 0 : 1;
    float oscale = path == 0 ? 0.125f : 1.0f;
    int t0 = bx * 128, n0 = by * 128;
    int tid = threadIdx.x;
    float alphab = g_alpha[path] * (1.0f / 127.0f) * oscale;

    int acc[2][8][4];
    imma_tile(A, Bw, t0, n0, dsm, acc);
    int warp = tid >> 5, lane = tid & 31;
    int wm = warp >> 1, wn = warp & 1;
#pragma unroll
    for (int mt = 0; mt < 2; mt++) {
        int r0 = t0 + wm * 32 + mt * 16 + (lane >> 2);
        int r1 = r0 + 8;
        float s0 = alphab * gamma[r0];
        float s1 = alphab * gamma[r1];
#pragma unroll
        for (int nt = 0; nt < 8; nt++) {
            int n = n0 + wn * 64 + nt * 8 + (lane & 3) * 2;
            write_qkv_pair((float)acc[mt][nt][0] * s0, (float)acc[mt][nt][1] * s0,
                           r0, n, nheads, rope, hob, lob);
            write_qkv_pair((float)acc[mt][nt][2] * s1, (float)acc[mt][nt][3] * s1,
                           r1, n, nheads, rope, hob, lob);
        }
    }
}

// ---------------- O-proj GEMM (pure IMMA, 2 blocks/SM, float out + residual) --
__global__ __launch_bounds__(256, 2) void gemm_o(
    float* __restrict__ outf, const float* __restrict__ resid) {
    extern __shared__ uint8_t dsm[];
    int t0 = blockIdx.x * 128, n0 = blockIdx.y * 128;
    int tid = threadIdx.x;
    float alphab = g_alpha[3] * (1.0f / 127.0f);

    int acc[2][8][4];
    imma_tile(g_xq_o, g_wq_o, t0, n0, dsm, acc);
    int warp = tid >> 5, lane = tid & 31;
    int wm = warp >> 1, wn = warp & 1;
#pragma unroll
    for (int mt = 0; mt < 2; mt++) {
        int r0 = t0 + wm * 32 + mt * 16 + (lane >> 2);
        int r1 = r0 + 8;
        float s0 = alphab * g_gamma_o[r0];
        float s1 = alphab * g_gamma_o[r1];
#pragma unroll
        for (int nt = 0; nt < 8; nt++) {
            int n = n0 + wn * 64 + nt * 8 + (lane & 3) * 2;
            const float* rr0 = resid + (size_t)r0 * HID + n;
            const float* rr1 = resid + (size_t)r1 * HID + n;
            *(float2*)&outf[(size_t)r0 * HID + n] =
                make_float2((float)acc[mt][nt][0] * s0 + rr0[0],
                            (float)acc[mt][nt][1] * s0 + rr0[1]);
            *(float2*)&outf[(size_t)r1 * HID + n] =
                make_float2((float)acc[mt][nt][2] * s1 + rr1[0],
                            (float)acc[mt][nt][3] * s1 + rr1[1]);
        }
    }
}

// ---------------- attention: flash, split-fp16 mma, 2 blocks/SM ----------------
#define SPITCH 72
#define ATTN_SMEM (36864 * 2)   // 73728 B
__global__ __launch_bounds__(256, 2) void attn_mma(float* __restrict__ out) {
    extern __shared__ __half ASM[];

    int tid = threadIdx.x;
    int warp = tid >> 5, lane = tid & 31;
    int qt = blockIdx.x;
    int bh = blockIdx.y;
    int b = bh / NQH, h = bh % NQH;
    int kvh = h / (NQH / NKVH);

    size_t qoff = ((size_t)(b * NQH + h) * SEQ + qt * 128) * HD;
    size_t kvoff = (size_t)(b * NKVH + kvh) * SEQ * HD;
    const __half* gbuf[4] = { g_kh + kvoff, g_kl + kvoff, g_vh + kvoff, g_vl + kvoff };

    __half* Qh = ASM;
    __half* Ql = ASM + 9216;
#pragma unroll
    for (int i = 0; i < 4; i++) {
        int slot = tid + i * 256;
        int r = slot >> 3, seg = slot & 7;
        *(float4*)&Qh[r * SPITCH + seg * 8] = *(const float4*)&g_qh[qoff + r * 64 + seg * 8];
        *(float4*)&Ql[r * SPITCH + seg * 8] = *(const float4*)&g_ql[qoff + r * 64 + seg * 8];
    }
    __syncthreads();

    {
        __half* sb = ASM + 18432;
#pragma unroll
        for (int i = 0; i < 8; i++) {
            int slot = tid + i * 256;
            int bufi = slot >> 9, r = (slot >> 3) & 63, seg = slot & 7;
            cp16(&sb[bufi * 4608 + r * SPITCH + seg * 8], &gbuf[bufi][r * 64 + seg * 8]);
        }
        cp_commit();
    }

    uint32_t qah[4][4], qal[4][4];
    int m0 = warp * 16;
#pragma unroll
    for (int kc = 0; kc < 4; kc++) {
        int r = m0 + (lane & 15), c = kc * 16 + (lane >> 4) * 8;
        ldmx4(qah[kc], smem_u32(&Qh[r * SPITCH + c]));
        ldmx4(qal[kc], smem_u32(&Ql[r * SPITCH + c]));
    }
    __syncthreads();

    float oacc[8][4];
#pragma unroll
    for (int nt = 0; nt < 8; nt++)
#pragma unroll
        for (int i = 0; i < 4; i++) oacc[nt][i] = 0.0f;
    float mrow0 = -1e30f, mrow1 = -1e30f, lrow0 = 0.0f, lrow1 = 0.0f;

    for (int kt = 0; kt < 8; kt++) {
        if (kt < 7) {
            __half* sb = ASM + (kt & 1) * 18432;
#pragma unroll
            for (int i = 0; i < 8; i++) {
                int slot = tid + i * 256;
                int bufi = slot >> 9, r = (slot >> 3) & 63, seg = slot & 7;
                cp16(&sb[bufi * 4608 + r * SPITCH + seg * 8],
                     &gbuf[bufi][((kt + 1) * 64 + r) * 64 + seg * 8]);
            }
            cp_commit();
            cp_wait<1>();
        } else {
            cp_wait<0>();
        }
        __syncthreads();
        __half* sb = ASM + ((kt + 1) & 1) * 18432;
        __half* Khs = sb;
        __half* Kls = sb + 4608;
        __half* Vhs = sb + 9216;
        __half* Vls = sb + 13824;

        float sacc[8][4];
#pragma unroll
        for (int nt = 0; nt < 8; nt++)
#pragma unroll
            for (int i = 0; i < 4; i++) sacc[nt][i] = 0.0f;
        int g = lane >> 3;
        int n_off = (g >= 2) ? 8 : 0, k_off = (g & 1) * 8;
#pragma unroll
        for (int nt2 = 0; nt2 < 4; nt2++) {
#pragma unroll
            for (int kc = 0; kc < 4; kc++) {
                uint32_t kbh[4], kbl[4];
                int r = nt2 * 16 + n_off + (lane & 7), c = kc * 16 + k_off;
                ldmx4(kbh, smem_u32(&Khs[r * SPITCH + c]));
                ldmx4(kbl, smem_u32(&Kls[r * SPITCH + c]));
                mma_f16(sacc[nt2 * 2],     qah[kc], kbh[0], kbh[1]);
                mma_f16(sacc[nt2 * 2],     qah[kc], kbl[0], kbl[1]);
                mma_f16(sacc[nt2 * 2],     qal[kc], kbh[0], kbh[1]);
                mma_f16(sacc[nt2 * 2 + 1], qah[kc], kbh[2], kbh[3]);
                mma_f16(sacc[nt2 * 2 + 1], qah[kc], kbl[2], kbl[3]);
                mma_f16(sacc[nt2 * 2 + 1], qal[kc], kbh[2], kbh[3]);
            }
        }

        float mx0 = -1e30f, mx1 = -1e30f;
#pragma unroll
        for (int nt = 0; nt < 8; nt++) {
            mx0 = fmaxf(mx0, fmaxf(sacc[nt][0], sacc[nt][1]));
            mx1 = fmaxf(mx1, fmaxf(sacc[nt][2], sacc[nt][3]));
        }
        mx0 = fmaxf(mx0, __shfl_xor_sync(0xffffffffu, mx0, 1));
        mx0 = fmaxf(mx0, __shfl_xor_sync(0xffffffffu, mx0, 2));
        mx1 = fmaxf(mx1, __shfl_xor_sync(0xffffffffu, mx1, 1));
        mx1 = fmaxf(mx1, __shfl_xor_sync(0xffffffffu, mx1, 2));
        float mn0 = fmaxf(mrow0, mx0), mn1 = fmaxf(mrow1, mx1);
        float e0 = __expf(mrow0 - mn0), e1 = __expf(mrow1 - mn1);
        mrow0 = mn0; mrow1 = mn1;

        float sum0 = 0.0f, sum1 = 0.0f;
        uint32_t pah[4][4], pal[4][4];
#pragma unroll
        for (int kc2 = 0; kc2 < 4; kc2++) {
            int nta = kc2 * 2, ntb = nta + 1;
            float p[8];
            p[0] = __expf(sacc[nta][0] - mn0); p[1] = __expf(sacc[nta][1] - mn0);
            p[2] = __expf(sacc[nta][2] - mn1); p[3] = __expf(sacc[nta][3] - mn1);
            p[4] = __expf(sacc[ntb][0] - mn0); p[5] = __expf(sacc[ntb][1] - mn0);
            p[6] = __expf(sacc[ntb][2] - mn1); p[7] = __expf(sacc[ntb][3] - mn1);
            __half ph[8], pl[8];
#pragma unroll
            for (int i = 0; i < 8; i++) split_h(p[i], ph[i], pl[i]);
            sum0 += p[0] + p[1] + p[4] + p[5];
            sum1 += p[2] + p[3] + p[6] + p[7];
            pah[kc2][0] = pack_h2(ph[0], ph[1]); pal[kc2][0] = pack_h2(pl[0], pl[1]);
            pah[kc2][1] = pack_h2(ph[2], ph[3]); pal[kc2][1] = pack_h2(pl[2], pl[3]);
            pah[kc2][2] = pack_h2(ph[4], ph[5]); pal[kc2][2] = pack_h2(pl[4], pl[5]);
            pah[kc2][3] = pack_h2(ph[6], ph[7]); pal[kc2][3] = pack_h2(pl[6], pl[7]);
        }
        sum0 += __shfl_xor_sync(0xffffffffu, sum0, 1);
        sum0 += __shfl_xor_sync(0xffffffffu, sum0, 2);
        sum1 += __shfl_xor_sync(0xffffffffu, sum1, 1);
        sum1 += __shfl_xor_sync(0xffffffffu, sum1, 2);
        lrow0 = lrow0 * e0 + sum0;
        lrow1 = lrow1 * e1 + sum1;

#pragma unroll
        for (int nt = 0; nt < 8; nt++) {
            oacc[nt][0] *= e0; oacc[nt][1] *= e0;
            oacc[nt][2] *= e1; oacc[nt][3] *= e1;
        }

#pragma unroll
        for (int kc2 = 0; kc2 < 4; kc2++) {
#pragma unroll
            for (int nt2 = 0; nt2 < 4; nt2++) {
                uint32_t vbh[4], vbl[4];
                int r = kc2 * 16 + (g & 1) * 8 + (lane & 7);
                int c = nt2 * 16 + ((g >= 2) ? 8 : 0);
                ldmx4t(vbh, smem_u32(&Vhs[r * SPITCH + c]));
                ldmx4t(vbl, smem_u32(&Vls[r * SPITCH + c]));
                mma_f16(oacc[nt2 * 2],     pah[kc2], vbh[0], vbh[1]);
                mma_f16(oacc[nt2 * 2],     pah[kc2], vbl[0], vbl[1]);
                mma_f16(oacc[nt2 * 2],     pal[kc2], vbh[0], vbh[1]);
                mma_f16(oacc[nt2 * 2 + 1], pah[kc2], vbh[2], vbh[3]);
                mma_f16(oacc[nt2 * 2 + 1], pah[kc2], vbl[2], vbl[3]);
                mma_f16(oacc[nt2 * 2 + 1], pal[kc2], vbh[2], vbh[3]);
            }
        }
        __syncthreads();
    }

    float inv0 = 1.0f / lrow0, inv1 = 1.0f / lrow1;
    int r0 = qt * 128 + m0 + (lane >> 2);
    int r1 = r0 + 8;
#pragma unroll
    for (int nt = 0; nt < 8; nt++) {
        int col = h * HD + nt * 8 + (lane & 3) * 2;
        float2 v0 = make_float2(oacc[nt][0] * inv0, oacc[nt][1] * inv0);
        float2 v1 = make_float2(oacc[nt][2] * inv1, oacc[nt][3] * inv1);
        *(float2*)&out[((size_t)b * SEQ + r0) * HID + col] = v0;
        *(float2*)&out[((size_t)b * SEQ + r1) * HID + col] = v1;
    }
}

// ---------------- launch ----------------
extern "C" void kernel_launch(void* const* d_in, const int* in_sizes, int n_in,
                              void* d_out, int out_size) {
    const float* x      = (const float*)d_in[0];
    const float* norm_w = (const float*)d_in[1];
    const float* q_w    = (const float*)d_in[2];
    const float* q_g    = (const float*)d_in[3];
    const float* k_w    = (const float*)d_in[4];
    const float* k_g    = (const float*)d_in[5];
    const float* v_w    = (const float*)d_in[6];
    const float* v_g    = (const float*)d_in[7];
    const float* o_w    = (const float*)d_in[8];
    const float* o_g    = (const float*)d_in[9];
    float* out = (float*)d_out;

    void* p_att;
    cudaGetSymbolAddress(&p_att, g_att);

    cudaFuncSetAttribute(gemm_qkv, cudaFuncAttributeMaxDynamicSharedMemorySize, GEMM_SMEM);
    cudaFuncSetAttribute(gemm_o, cudaFuncAttributeMaxDynamicSharedMemorySize, GEMM_SMEM);
    cudaFuncSetAttribute(attn_mma, cudaFuncAttributeMaxDynamicSharedMemorySize, ATTN_SMEM);

    // 1. weight alphas + rope tables (fused, 1024-thread blocks)
    prep_all<<<68, 1024>>>(q_w, k_w, v_w, o_w);

    // 2. weight ternary quant
    wquant_all<<<(2 * HID * HID + 2 * KVDIM * HID + 255) / 256, 256>>>(q_w, k_w, v_w, o_w);

    // 3. activation double-rmsnorm + int8 quant
    act_quant_qkv<<<T_TOKENS / 8, 256>>>(x, norm_w, q_g, k_g, v_g);

    // 4. fused QKV GEMMs (pure IMMA, 2 blocks/SM; rope + hi/lo split epilogue)
    gemm_qkv<<<896, 256, GEMM_SMEM>>>();

    // 5. attention (2 blocks/SM)
    attn_mma<<<dim3(SEQ / 128, BATCH * NQH), 256, ATTN_SMEM>>>((float*)p_att);

    // 6. O-proj quant + GEMM + residual
    act_quant_o<<<T_TOKENS / 8, 256>>>(o_g);
    gemm_o<<<dim3(128, 5), 256, GEMM_SMEM>>>(out, x);
}